// round 2
// baseline (speedup 1.0000x reference)
#include <cuda_runtime.h>
#include <cuda_fp16.h>
#include <cstdint>

#define DI __device__ __forceinline__

// scratch (no allocation allowed -> device globals)
static __device__ float  g_wv[32u * 512u * 512u];   // w_v [b][l][d]
static __device__ __half g_woT[512 * 32];           // w_o packed: d4*128 + n*4 + (d&3)
static __device__ float  g_e[32 * 32 * 512];        // e     [b][n][l]
static __device__ float  g_alpha[32 * 32 * 512];    // alpha [b][n][l]

DI float tanh_apx(float x) { float r; asm("tanh.approx.f32 %0, %1;" : "=f"(r) : "f"(x)); return r; }
DI uint32_t f2tf(float x) { uint32_t r; asm("cvt.rna.tf32.f32 %0, %1;" : "=r"(r) : "f"(x)); return r; }
DI void mma8(float c[4], const uint32_t a[4], const uint32_t b[2]) {
    asm volatile("mma.sync.aligned.m16n8k8.row.col.f32.tf32.tf32.f32 "
                 "{%0,%1,%2,%3}, {%4,%5,%6,%7}, {%8,%9}, {%0,%1,%2,%3};"
                 : "+f"(c[0]), "+f"(c[1]), "+f"(c[2]), "+f"(c[3])
                 : "r"(a[0]), "r"(a[1]), "r"(a[2]), "r"(a[3]), "r"(b[0]), "r"(b[1]));
}
DI void cpa16(void* s, const void* g) {
    uint32_t sa = (uint32_t)__cvta_generic_to_shared(s);
    asm volatile("cp.async.ca.shared.global [%0], [%1], 16;\n" :: "r"(sa), "l"(g));
}
DI void cpcommit() { asm volatile("cp.async.commit_group;\n"); }
DI void cpwait0()  { asm volatile("cp.async.wait_group 0;\n"); }

// ---------- K1: w_o = emb @ Wo + b, store half packed ----------
__global__ void k1_wo(const float* __restrict__ emb, const float* __restrict__ Wo,
                      const float* __restrict__ Wob) {
    int idx = blockIdx.x * 256 + threadIdx.x;  // 4096
    int n = idx >> 7, d4 = idx & 127, d0 = d4 * 4;
    float4 a = make_float4(Wob[d0], Wob[d0+1], Wob[d0+2], Wob[d0+3]);
    const float* eb = emb + n * 512;
#pragma unroll 4
    for (int k = 0; k < 512; k++) {
        float e = __ldg(eb + k);
        float4 w = *(const float4*)(Wo + k * 512 + d0);
        a.x += e*w.x; a.y += e*w.y; a.z += e*w.z; a.w += e*w.w;
    }
    __half2* p = (__half2*)(g_woT + d4 * 128 + n * 4);
    p[0] = __floats2half2_rn(a.x, a.y);
    p[1] = __floats2half2_rn(a.z, a.w);
}

// ---------- K2: w_v = inp @ Wv + b (tf32 mma) ----------
#define AST 20
#define BST 136
__global__ __launch_bounds__(256, 2)
void k2_gemm(const float* __restrict__ A, const float* __restrict__ B,
             const float* __restrict__ bias) {
    __shared__ float As[2][128 * AST];
    __shared__ float Bs[2][16 * BST];
    __shared__ float bias_s[128];
    const int tid = threadIdx.x;
    const int bm0 = blockIdx.y * 128, bn0 = blockIdx.x * 128;
    const int warp = tid >> 5, lane = tid & 31;
    const int wm = warp >> 2, wn = warp & 3;
    const int g = lane >> 2, tig = lane & 3;
    if (tid < 128) bias_s[tid] = bias[bn0 + tid];

    auto stage = [&](int s, int k0) {
#pragma unroll
        for (int i = 0; i < 2; i++) {
            int c = tid + 256 * i;
            int r = c >> 2, cc = c & 3;
            cpa16(&As[s][r * AST + cc * 4], A + (size_t)(bm0 + r) * 512 + k0 + cc * 4);
        }
#pragma unroll
        for (int i = 0; i < 2; i++) {
            int c = tid + 256 * i;
            int r = c >> 5, cc = c & 31;
            cpa16(&Bs[s][r * BST + cc * 4], B + (size_t)(k0 + r) * 512 + bn0 + cc * 4);
        }
        cpcommit();
    };

    float c[4][4][4];
#pragma unroll
    for (int mi = 0; mi < 4; mi++)
#pragma unroll
        for (int ni = 0; ni < 4; ni++)
#pragma unroll
            for (int j = 0; j < 4; j++) c[mi][ni][j] = 0.f;

    stage(0, 0);
    for (int s = 0; s < 32; s++) {
        cpwait0();
        __syncthreads();
        if (s + 1 < 32) stage((s + 1) & 1, (s + 1) * 16);
        const int buf = s & 1;
#pragma unroll
        for (int kk = 0; kk < 16; kk += 8) {
            uint32_t af[4][4], bf[4][2];
#pragma unroll
            for (int mi = 0; mi < 4; mi++) {
                int r0 = wm * 64 + mi * 16 + g;
                af[mi][0] = f2tf(As[buf][r0 * AST + kk + tig]);
                af[mi][1] = f2tf(As[buf][(r0 + 8) * AST + kk + tig]);
                af[mi][2] = f2tf(As[buf][r0 * AST + kk + tig + 4]);
                af[mi][3] = f2tf(As[buf][(r0 + 8) * AST + kk + tig + 4]);
            }
#pragma unroll
            for (int ni = 0; ni < 4; ni++) {
                int c0 = wn * 32 + ni * 8 + g;
                bf[ni][0] = f2tf(Bs[buf][(kk + tig) * BST + c0]);
                bf[ni][1] = f2tf(Bs[buf][(kk + tig + 4) * BST + c0]);
            }
#pragma unroll
            for (int mi = 0; mi < 4; mi++)
#pragma unroll
                for (int ni = 0; ni < 4; ni++) mma8(c[mi][ni], af[mi], bf[ni]);
        }
        __syncthreads();
    }
#pragma unroll
    for (int mi = 0; mi < 4; mi++) {
        int row = bm0 + wm * 64 + mi * 16 + g;
#pragma unroll
        for (int ni = 0; ni < 4; ni++) {
            int colL = wn * 32 + ni * 8 + 2 * tig;
            float b0 = bias_s[colL], b1 = bias_s[colL + 1];
            *(float2*)(g_wv + (size_t)row * 512 + bn0 + colL) =
                make_float2(c[mi][ni][0] + b0, c[mi][ni][1] + b1);
            *(float2*)(g_wv + (size_t)(row + 8) * 512 + bn0 + colL) =
                make_float2(c[mi][ni][2] + b0, c[mi][ni][3] + b1);
        }
    }
}

// ---------- K3: e[b,n,l] = sum_d tanh(wo[n,d]+wv[b,l,d])*We[d] ----------
__global__ __launch_bounds__(128)
void k3_tanh(const float* __restrict__ We) {
    __shared__ __half wo_s[512 * 32];  // 32 KB
    __shared__ float  v_s[4 * 512];    // 8 KB
    __shared__ float  we_s[512];       // 2 KB
    const int b = blockIdx.y, l0 = blockIdx.x * 4, tid = threadIdx.x;
    { const uint4* s = (const uint4*)g_woT; uint4* d = (uint4*)wo_s;
#pragma unroll
      for (int i = 0; i < 16; i++) d[tid + 128 * i] = s[tid + 128 * i]; }
    { const float4* s = (const float4*)(g_wv + ((size_t)b * 512 + l0) * 512);
      float4* d = (float4*)v_s;
#pragma unroll
      for (int i = 0; i < 4; i++) d[tid + 128 * i] = s[tid + 128 * i]; }
    ((float4*)we_s)[tid] = ((const float4*)We)[tid];
    __syncthreads();
    const int w = tid >> 5, n = tid & 31;
    const float* vr = v_s + w * 512;
    float acc = 0.f;
#pragma unroll 4
    for (int d4 = 0; d4 < 128; d4++) {
        float4 wv = *(const float4*)(vr + d4 * 4);
        uint2 wo = *(const uint2*)(wo_s + d4 * 128 + n * 4);
        float2 o01 = __half22float2(*(__half2*)&wo.x);
        float2 o23 = __half22float2(*(__half2*)&wo.y);
        const float* we = we_s + d4 * 4;
        acc += tanh_apx(o01.x + wv.x) * we[0];
        acc += tanh_apx(o01.y + wv.y) * we[1];
        acc += tanh_apx(o23.x + wv.z) * we[2];
        acc += tanh_apx(o23.y + wv.w) * we[3];
    }
    g_e[((size_t)b * 32 + n) * 512 + l0 + w] = acc;
}

// ---------- K4: softmax over l ----------
__global__ __launch_bounds__(128)
void k4_softmax() {
    const int row = blockIdx.y * 32 + blockIdx.x, tid = threadIdx.x;
    const float* e = g_e + (size_t)row * 512;
    float* a = g_alpha + (size_t)row * 512;
    __shared__ float red[128];
    float4 x = ((const float4*)e)[tid];
    float m = fmaxf(fmaxf(x.x, x.y), fmaxf(x.z, x.w));
    red[tid] = m; __syncthreads();
    for (int s = 64; s > 0; s >>= 1) { if (tid < s) red[tid] = fmaxf(red[tid], red[tid + s]); __syncthreads(); }
    m = red[0]; __syncthreads();
    x.x = __expf(x.x - m); x.y = __expf(x.y - m);
    x.z = __expf(x.z - m); x.w = __expf(x.w - m);
    red[tid] = x.x + x.y + x.z + x.w; __syncthreads();
    for (int s = 64; s > 0; s >>= 1) { if (tid < s) red[tid] += red[tid + s]; __syncthreads(); }
    float inv = 1.f / red[0];
    x.x *= inv; x.y *= inv; x.z *= inv; x.w *= inv;
    ((float4*)a)[tid] = x;
}

// ---------- K5: vf[b,n,d] = sum_l alpha[b,n,l]*inp[b,l,d] ----------
__global__ __launch_bounds__(128)
void k5_vf(const float* __restrict__ inp, float* __restrict__ out) {
    const int b = blockIdx.x, tid = threadIdx.x;
    const int d = blockIdx.y * 128 + tid;
    __shared__ float a_s[32][128];
    float acc[32];
#pragma unroll
    for (int n = 0; n < 32; n++) acc[n] = 0.f;
    for (int lc = 0; lc < 512; lc += 128) {
        __syncthreads();
#pragma unroll
        for (int n = 0; n < 32; n++) a_s[n][tid] = g_alpha[((size_t)b * 32 + n) * 512 + lc + tid];
        __syncthreads();
#pragma unroll 4
        for (int l = 0; l < 128; l++) {
            float x = inp[((size_t)b * 512 + lc + l) * 512 + d];
#pragma unroll
            for (int n = 0; n < 32; n++) acc[n] += a_s[n][l] * x;
        }
    }
#pragma unroll
    for (int n = 0; n < 32; n++) out[((size_t)b * 32 + n) * 512 + d] = acc[n];
}

// ---------- K6: logits = vf @ Wc + b ----------
__global__ __launch_bounds__(128)
void k6_logits(const float* __restrict__ Wc, const float* __restrict__ Wcb,
               const float* __restrict__ vf, float* __restrict__ out) {
    const int row = blockIdx.x, tid = threadIdx.x;
    __shared__ float v_s[512];
    ((float4*)v_s)[tid] = ((const float4*)(vf + (size_t)row * 512))[tid];
    __syncthreads();
    if (tid < 97) {
        float acc = Wcb[tid];
#pragma unroll 8
        for (int k = 0; k < 512; k++) acc += v_s[k] * Wc[k * 97 + tid];
        out[(size_t)row * 97 + tid] = acc;
    }
}

extern "C" void kernel_launch(void* const* d_in, const int* in_sizes, int n_in,
                              void* d_out, int out_size) {
    const float* inp  = (const float*)d_in[0];
    const float* emb  = (const float*)d_in[1];
    const float* Wo_w = (const float*)d_in[2];
    const float* Wo_b = (const float*)d_in[3];
    const float* Wv_w = (const float*)d_in[4];
    const float* Wv_b = (const float*)d_in[5];
    const float* We_w = (const float*)d_in[6];
    const float* Wc_w = (const float*)d_in[8];
    const float* Wc_b = (const float*)d_in[9];
    float* out = (float*)d_out;
    float* vf = out;                         // (32*32, 512)
    float* logits = out + 32 * 32 * 512;     // (32*32, 97)

    k1_wo<<<16, 256>>>(emb, Wo_w, Wo_b);
    k2_gemm<<<dim3(4, 128), 256>>>(inp, Wv_w, Wv_b);
    k3_tanh<<<dim3(128, 32), 128>>>(We_w);
    k4_softmax<<<dim3(32, 32), 128>>>();
    k5_vf<<<dim3(32, 4), 128>>>(inp, vf);
    k6_logits<<<1024, 128>>>(Wc_w, Wc_b, vf, logits);
}

// round 3
// speedup vs baseline: 1.3549x; 1.3549x over previous
#include <cuda_runtime.h>
#include <cuda_fp16.h>
#include <cstdint>

#define DI __device__ __forceinline__

// scratch (device globals; no allocation allowed)
static __device__ __half2 g_wvh[32u * 512u * 256u];   // w_v half2 [b*512+l][d/2]  (16.8MB)
static __device__ __half  g_wo2[512 * 32];            // w_o packed [d8][n][4xhalf2]
static __device__ float   g_e[32 * 32 * 512];         // e     [b][n][l]
static __device__ float   g_alpha[32 * 32 * 512];     // alpha [b][n][l]
static __device__ float   g_part[32 * 4 * 32 * 512];  // vf partials [b][lc][n][d]

DI __half2 tanh2(__half2 x) {
    uint32_t r, xi = *(uint32_t*)&x;
    asm("tanh.approx.f16x2 %0, %1;" : "=r"(r) : "r"(xi));
    return *(__half2*)&r;
}
DI uint32_t f2tf(float x) { uint32_t r; asm("cvt.rna.tf32.f32 %0, %1;" : "=r"(r) : "f"(x)); return r; }
DI void mma8(float c[4], const uint32_t a[4], const uint32_t b[2]) {
    asm volatile("mma.sync.aligned.m16n8k8.row.col.f32.tf32.tf32.f32 "
                 "{%0,%1,%2,%3}, {%4,%5,%6,%7}, {%8,%9}, {%0,%1,%2,%3};"
                 : "+f"(c[0]), "+f"(c[1]), "+f"(c[2]), "+f"(c[3])
                 : "r"(a[0]), "r"(a[1]), "r"(a[2]), "r"(a[3]), "r"(b[0]), "r"(b[1]));
}
DI void cpa16(void* s, const void* g) {
    uint32_t sa = (uint32_t)__cvta_generic_to_shared(s);
    asm volatile("cp.async.ca.shared.global [%0], [%1], 16;\n" :: "r"(sa), "l"(g));
}
DI void cpcommit() { asm volatile("cp.async.commit_group;\n"); }
DI void cpwait0()  { asm volatile("cp.async.wait_group 0;\n"); }

// ---------- K1: w_o = emb @ Wo + b, packed half [d8][n][4*half2] ----------
__global__ void k1_wo(const float* __restrict__ emb, const float* __restrict__ Wo,
                      const float* __restrict__ Wob) {
    int idx = blockIdx.x * 256 + threadIdx.x;  // 4096
    int n = idx >> 7, d4 = idx & 127, d0 = d4 * 4;
    float4 a = make_float4(Wob[d0], Wob[d0+1], Wob[d0+2], Wob[d0+3]);
    const float* eb = emb + n * 512;
#pragma unroll 4
    for (int k = 0; k < 512; k++) {
        float e = __ldg(eb + k);
        float4 w = *(const float4*)(Wo + k * 512 + d0);
        a.x += e*w.x; a.y += e*w.y; a.z += e*w.z; a.w += e*w.w;
    }
    __half2 h01 = __floats2half2_rn(a.x, a.y);
    __half2 h23 = __floats2half2_rn(a.z, a.w);
    int d8 = d4 >> 1;
    uint2 v = make_uint2(*(uint32_t*)&h01, *(uint32_t*)&h23);
    ((uint2*)g_wo2)[d8 * 64 + n * 2 + (d4 & 1)] = v;
}

// ---------- K2: w_v = inp @ Wv + b (tf32 mma), half2 output ----------
#define AST 20
#define BST 136
__global__ __launch_bounds__(256, 2)
void k2_gemm(const float* __restrict__ A, const float* __restrict__ B,
             const float* __restrict__ bias) {
    __shared__ float As[2][128 * AST];
    __shared__ float Bs[2][16 * BST];
    __shared__ float bias_s[128];
    const int tid = threadIdx.x;
    const int bm0 = blockIdx.y * 128, bn0 = blockIdx.x * 128;
    const int warp = tid >> 5, lane = tid & 31;
    const int wm = warp >> 2, wn = warp & 3;
    const int g = lane >> 2, tig = lane & 3;
    if (tid < 128) bias_s[tid] = bias[bn0 + tid];

    auto stage = [&](int s, int k0) {
#pragma unroll
        for (int i = 0; i < 2; i++) {
            int c = tid + 256 * i;
            int r = c >> 2, cc = c & 3;
            cpa16(&As[s][r * AST + cc * 4], A + (size_t)(bm0 + r) * 512 + k0 + cc * 4);
        }
#pragma unroll
        for (int i = 0; i < 2; i++) {
            int c = tid + 256 * i;
            int r = c >> 5, cc = c & 31;
            cpa16(&Bs[s][r * BST + cc * 4], B + (size_t)(k0 + r) * 512 + bn0 + cc * 4);
        }
        cpcommit();
    };

    float c[4][4][4];
#pragma unroll
    for (int mi = 0; mi < 4; mi++)
#pragma unroll
        for (int ni = 0; ni < 4; ni++)
#pragma unroll
            for (int j = 0; j < 4; j++) c[mi][ni][j] = 0.f;

    stage(0, 0);
    for (int s = 0; s < 32; s++) {
        cpwait0();
        __syncthreads();
        if (s + 1 < 32) stage((s + 1) & 1, (s + 1) * 16);
        const int buf = s & 1;
#pragma unroll
        for (int kk = 0; kk < 16; kk += 8) {
            uint32_t af[4][4], bf[4][2];
#pragma unroll
            for (int mi = 0; mi < 4; mi++) {
                int r0 = wm * 64 + mi * 16 + g;
                af[mi][0] = f2tf(As[buf][r0 * AST + kk + tig]);
                af[mi][1] = f2tf(As[buf][(r0 + 8) * AST + kk + tig]);
                af[mi][2] = f2tf(As[buf][r0 * AST + kk + tig + 4]);
                af[mi][3] = f2tf(As[buf][(r0 + 8) * AST + kk + tig + 4]);
            }
#pragma unroll
            for (int ni = 0; ni < 4; ni++) {
                int c0 = wn * 32 + ni * 8 + g;
                bf[ni][0] = f2tf(Bs[buf][(kk + tig) * BST + c0]);
                bf[ni][1] = f2tf(Bs[buf][(kk + tig + 4) * BST + c0]);
            }
#pragma unroll
            for (int mi = 0; mi < 4; mi++)
#pragma unroll
                for (int ni = 0; ni < 4; ni++) mma8(c[mi][ni], af[mi], bf[ni]);
        }
        __syncthreads();
    }
#pragma unroll
    for (int mi = 0; mi < 4; mi++) {
        int row = bm0 + wm * 64 + mi * 16 + g;
#pragma unroll
        for (int ni = 0; ni < 4; ni++) {
            int colL = wn * 32 + ni * 8 + 2 * tig;           // even
            float b0 = bias_s[colL], b1 = bias_s[colL + 1];
            int colh = (bn0 + colL) >> 1;
            g_wvh[(size_t)row * 256 + colh] =
                __floats2half2_rn(c[mi][ni][0] + b0, c[mi][ni][1] + b1);
            g_wvh[(size_t)(row + 8) * 256 + colh] =
                __floats2half2_rn(c[mi][ni][2] + b0, c[mi][ni][3] + b1);
        }
    }
}

// ---------- K3: e[b,n,l] = sum_d tanh(wo+wv)*We, f16x2 tanh ----------
__global__ __launch_bounds__(256)
void k3_tanh(const float* __restrict__ We) {
    __shared__ uint4 wo_s[64 * 32];   // [d8][n] : 4 half2 = 8 d  (32KB)
    __shared__ uint4 v_s[8][64];      // 8 rows x 64 uint4 (8 d each)  (8KB)
    __shared__ float we_s[512];       // 2KB
    const int b = blockIdx.y, l0 = blockIdx.x * 8, tid = threadIdx.x;
    { const uint4* s = (const uint4*)g_wo2;
#pragma unroll
      for (int i = 0; i < 8; i++) wo_s[tid + 256 * i] = s[tid + 256 * i]; }
    { const uint4* s = (const uint4*)(g_wvh + ((size_t)b * 512 + l0) * 256);
#pragma unroll
      for (int i = 0; i < 2; i++) ((uint4*)v_s)[tid + 256 * i] = s[tid + 256 * i]; }
    if (tid < 128) ((float4*)we_s)[tid] = ((const float4*)We)[tid];
    __syncthreads();
    const int w = tid >> 5, n = tid & 31;
    float acc = 0.f;
#pragma unroll 4
    for (int d8 = 0; d8 < 64; d8++) {
        uint4 wo = wo_s[d8 * 32 + n];
        uint4 wv = v_s[w][d8];
        float4 we0 = ((const float4*)we_s)[d8 * 2];
        float4 we1 = ((const float4*)we_s)[d8 * 2 + 1];
        const __half2* wop = (const __half2*)&wo;
        const __half2* wvp = (const __half2*)&wv;
        float2 t0 = __half22float2(tanh2(__hadd2(wop[0], wvp[0])));
        float2 t1 = __half22float2(tanh2(__hadd2(wop[1], wvp[1])));
        float2 t2 = __half22float2(tanh2(__hadd2(wop[2], wvp[2])));
        float2 t3 = __half22float2(tanh2(__hadd2(wop[3], wvp[3])));
        acc = fmaf(t0.x, we0.x, acc); acc = fmaf(t0.y, we0.y, acc);
        acc = fmaf(t1.x, we0.z, acc); acc = fmaf(t1.y, we0.w, acc);
        acc = fmaf(t2.x, we1.x, acc); acc = fmaf(t2.y, we1.y, acc);
        acc = fmaf(t3.x, we1.z, acc); acc = fmaf(t3.y, we1.w, acc);
    }
    g_e[((size_t)b * 32 + n) * 512 + l0 + w] = acc;
}

// ---------- K4: softmax over l (shuffle reductions) ----------
__global__ __launch_bounds__(128)
void k4_softmax() {
    const int row = blockIdx.x, tid = threadIdx.x;
    const int wid = tid >> 5, lane = tid & 31;
    const float* e = g_e + (size_t)row * 512;
    float* a = g_alpha + (size_t)row * 512;
    __shared__ float red[4];
    float4 x = ((const float4*)e)[tid];
    float m = fmaxf(fmaxf(x.x, x.y), fmaxf(x.z, x.w));
#pragma unroll
    for (int o = 16; o; o >>= 1) m = fmaxf(m, __shfl_xor_sync(~0u, m, o));
    if (lane == 0) red[wid] = m;
    __syncthreads();
    m = fmaxf(fmaxf(red[0], red[1]), fmaxf(red[2], red[3]));
    __syncthreads();
    x.x = __expf(x.x - m); x.y = __expf(x.y - m);
    x.z = __expf(x.z - m); x.w = __expf(x.w - m);
    float s = x.x + x.y + x.z + x.w;
#pragma unroll
    for (int o = 16; o; o >>= 1) s += __shfl_xor_sync(~0u, s, o);
    if (lane == 0) red[wid] = s;
    __syncthreads();
    float inv = 1.f / (red[0] + red[1] + red[2] + red[3]);
    x.x *= inv; x.y *= inv; x.z *= inv; x.w *= inv;
    ((float4*)a)[tid] = x;
}

// ---------- K5a: vf partials over 128-l chunks ----------
__global__ __launch_bounds__(128)
void k5a_vf(const float* __restrict__ inp) {
    const int b = blockIdx.x, tid = threadIdx.x;
    const int d = blockIdx.y * 128 + tid;
    const int lc = blockIdx.z, lc0 = lc * 128;
    __shared__ float a_s[32][128];
    float acc[32];
#pragma unroll
    for (int n = 0; n < 32; n++) acc[n] = 0.f;
#pragma unroll
    for (int n = 0; n < 32; n++) a_s[n][tid] = g_alpha[((size_t)b * 32 + n) * 512 + lc0 + tid];
    __syncthreads();
    const float* ib = inp + ((size_t)b * 512 + lc0) * 512 + d;
#pragma unroll 2
    for (int l4 = 0; l4 < 32; l4++) {
        float x0 = ib[(l4 * 4 + 0) * 512];
        float x1 = ib[(l4 * 4 + 1) * 512];
        float x2 = ib[(l4 * 4 + 2) * 512];
        float x3 = ib[(l4 * 4 + 3) * 512];
#pragma unroll
        for (int n = 0; n < 32; n++) {
            float4 a4 = ((const float4*)a_s[n])[l4];
            acc[n] = fmaf(a4.x, x0, acc[n]);
            acc[n] = fmaf(a4.y, x1, acc[n]);
            acc[n] = fmaf(a4.z, x2, acc[n]);
            acc[n] = fmaf(a4.w, x3, acc[n]);
        }
    }
#pragma unroll
    for (int n = 0; n < 32; n++)
        g_part[(((size_t)b * 4 + lc) * 32 + n) * 512 + d] = acc[n];
}

// ---------- K5b: reduce 4 partials -> vf ----------
__global__ __launch_bounds__(256)
void k5b_red(float* __restrict__ vf) {
    int i = blockIdx.x * 256 + threadIdx.x;      // float4 index, 131072 total
    int b = i >> 12, r = i & 4095;               // 32*512/4 = 4096 float4 per b
    const float4* p = (const float4*)g_part;
    float4 s0 = p[(size_t)(b * 4 + 0) * 4096 + r];
    float4 s1 = p[(size_t)(b * 4 + 1) * 4096 + r];
    float4 s2 = p[(size_t)(b * 4 + 2) * 4096 + r];
    float4 s3 = p[(size_t)(b * 4 + 3) * 4096 + r];
    float4 o;
    o.x = (s0.x + s1.x) + (s2.x + s3.x);
    o.y = (s0.y + s1.y) + (s2.y + s3.y);
    o.z = (s0.z + s1.z) + (s2.z + s3.z);
    o.w = (s0.w + s1.w) + (s2.w + s3.w);
    ((float4*)vf)[i] = o;
}

// ---------- K6: logits = vf @ Wc + b ----------
__global__ __launch_bounds__(128)
void k6_logits(const float* __restrict__ Wc, const float* __restrict__ Wcb,
               const float* __restrict__ vf, float* __restrict__ out) {
    const int row = blockIdx.x, tid = threadIdx.x;
    __shared__ float v_s[512];
    ((float4*)v_s)[tid] = ((const float4*)(vf + (size_t)row * 512))[tid];
    __syncthreads();
    if (tid < 97) {
        float a0 = Wcb[tid], a1 = 0.f, a2 = 0.f, a3 = 0.f;
#pragma unroll 4
        for (int k = 0; k < 128; k++) {
            int k4 = k * 4;
            a0 = fmaf(v_s[k4 + 0], Wc[(k4 + 0) * 97 + tid], a0);
            a1 = fmaf(v_s[k4 + 1], Wc[(k4 + 1) * 97 + tid], a1);
            a2 = fmaf(v_s[k4 + 2], Wc[(k4 + 2) * 97 + tid], a2);
            a3 = fmaf(v_s[k4 + 3], Wc[(k4 + 3) * 97 + tid], a3);
        }
        out[(size_t)row * 97 + tid] = (a0 + a1) + (a2 + a3);
    }
}

extern "C" void kernel_launch(void* const* d_in, const int* in_sizes, int n_in,
                              void* d_out, int out_size) {
    const float* inp  = (const float*)d_in[0];
    const float* emb  = (const float*)d_in[1];
    const float* Wo_w = (const float*)d_in[2];
    const float* Wo_b = (const float*)d_in[3];
    const float* Wv_w = (const float*)d_in[4];
    const float* Wv_b = (const float*)d_in[5];
    const float* We_w = (const float*)d_in[6];
    const float* Wc_w = (const float*)d_in[8];
    const float* Wc_b = (const float*)d_in[9];
    float* out = (float*)d_out;
    float* vf = out;                         // (32*32, 512)
    float* logits = out + 32 * 32 * 512;     // (32*32, 97)

    k1_wo<<<16, 256>>>(emb, Wo_w, Wo_b);
    k2_gemm<<<dim3(4, 128), 256>>>(inp, Wv_w, Wv_b);
    k3_tanh<<<dim3(64, 32), 256>>>(We_w);
    k4_softmax<<<1024, 128>>>();
    k5a_vf<<<dim3(32, 4, 4), 128>>>(inp);
    k5b_red<<<512, 256>>>(vf);
    k6_logits<<<1024, 128>>>(Wc_w, Wc_b, vf, logits);
}